// round 3
// baseline (speedup 1.0000x reference)
#include <cuda_runtime.h>
#include <cuda_bf16.h>

#define TT 2048
#define DD 64
#define EE 4
#define WW 9           // 2*EE+1
#define BMAX 131072

// counting-sort scratch (static device globals: alloc-free rule)
__device__ int   g_hist[TT];
__device__ int   g_cursor[TT];
__device__ float g_xs[BMAX];
__device__ int   g_qs[BMAX];

__device__ __forceinline__ unsigned long long pack2(float a, float b) {
    unsigned long long r;
    asm("mov.b64 %0, {%1, %2};" : "=l"(r) : "f"(a), "f"(b));
    return r;
}

__device__ __forceinline__ int bin_of(float xv, float e0, float invstep) {
    int c = __float2int_rn((xv - e0) * invstep);
    return max(0, min(c, TT - 1));
}

// ---- pass 1: zero histogram ----
__global__ void zero_hist_kernel() {
    int i = blockIdx.x * blockDim.x + threadIdx.x;
    if (i < TT) g_hist[i] = 0;
}

// ---- pass 2: histogram of bin keys ----
__global__ void hist_kernel(const float* __restrict__ x,
                            const float* __restrict__ ev, int B) {
    int i = blockIdx.x * blockDim.x + threadIdx.x;
    if (i >= B) return;
    const float e0 = __ldg(ev);
    const float invstep = (float)(TT - 1) / (__ldg(ev + TT - 1) - e0);
    atomicAdd(&g_hist[bin_of(__ldg(x + i), e0, invstep)], 1);
}

// ---- pass 3: exclusive scan (single block, 1024 threads, 2 bins/thread) ----
__global__ void scan_kernel() {
    __shared__ int p[1024];
    const int t = threadIdx.x;
    const int a = g_hist[2 * t];
    const int b = g_hist[2 * t + 1];
    p[t] = a + b;
    __syncthreads();
    #pragma unroll
    for (int off = 1; off < 1024; off <<= 1) {
        int v = (t >= off) ? p[t - off] : 0;
        __syncthreads();
        p[t] += v;
        __syncthreads();
    }
    const int excl = p[t] - (a + b);     // exclusive prefix of pair t
    g_cursor[2 * t]     = excl;
    g_cursor[2 * t + 1] = excl + a;
}

// ---- pass 4: scatter queries into bin order ----
__global__ void scatter_kernel(const float* __restrict__ x,
                               const float* __restrict__ ev, int B) {
    int i = blockIdx.x * blockDim.x + threadIdx.x;
    if (i >= B) return;
    const float e0 = __ldg(ev);
    const float invstep = (float)(TT - 1) / (__ldg(ev + TT - 1) - e0);
    const float xv = __ldg(x + i);
    const int pos = atomicAdd(&g_cursor[bin_of(xv, e0, invstep)], 1);
    g_xs[pos] = xv;
    g_qs[pos] = i;
}

// ---- pass 5: main kernel over bin-sorted queries ----
// 4 queries/warp (lane group g = lane>>3), each lane owns float4 slots {sub, sub+8}.
template<bool SORTED>
__global__ void __launch_bounds__(256)
hwnet_kernel(const float* __restrict__ x,
             const float* __restrict__ ev,
             const float* __restrict__ tk,
             const float* __restrict__ vt,
             float* __restrict__ out,
             int B)
{
    const int lane = threadIdx.x & 31;
    const int warp = threadIdx.x >> 5;
    const int g    = lane >> 3;
    const int sub  = lane & 7;

    int p = (blockIdx.x * 8 + warp) * 4 + g;
    if (p >= B) p = B - 1;               // clamp: no lane exit, warp-sync safe

    float xv; int q;
    if (SORTED) { xv = g_xs[p]; q = g_qs[p]; }
    else        { q = p; xv = __ldg(x + q); }

    const float e0 = __ldg(ev);
    const float eL = __ldg(ev + TT - 1);
    const float step    = (eL - e0) * (1.0f / (TT - 1));
    const float invstep = (float)(TT - 1) / (eL - e0);

    // analytic candidate, verified with 3 exact-table probes (first-min tie-break)
    int cand = __float2int_rn((xv - e0) * invstep);
    cand = max(0, min(cand, TT - 1));
    const int j0 = max(cand - 1, 0);
    const int j2 = min(cand + 1, TT - 1);

    int idx = j0;
    float d  = xv - __ldg(ev + j0);
    float best = d * d;
    d = xv - __ldg(ev + cand);
    float dd = d * d;
    if (cand > j0 && dd < best) { best = dd; idx = cand; }
    d = xv - __ldg(ev + j2);
    dd = d * d;
    if (j2 > cand && dd < best) { idx = j2; }

    const float nt = -__ldg(tk + idx);   // takecare at UNclipped idx (matches ref)
    const int ic = min(max(idx, EE), TT - 1 - EE);

    // window weights from analytic ev: poly-exp fast path, exact exp when clipped
    const float d0 = (xv - e0) - (float)(ic - EE) * step;
    float w[WW];
    #pragma unroll
    for (int k = 0; k < WW; ++k) {
        float dk = d0 - (float)k * step;
        float l = dk * dk * nt;
        w[k] = __fmaf_rn(l, __fmaf_rn(l, 0.5f, 1.0f), 1.0f);  // 1 + l + l^2/2
    }
    if (__any_sync(0xFFFFFFFFu, ic != idx)) {
        #pragma unroll
        for (int k = 0; k < WW; ++k) {
            float dk = d0 - (float)k * step;
            w[k] = __expf(dk * dk * nt);
        }
    }

    float s = ((w[0] + w[1]) + (w[2] + w[3])) + ((w[4] + w[5]) + (w[6] + w[7])) + w[8];
    const float inv = __fdividef(1.0f, s);

    // weighted gather over the 9-row window, packed f32x2 FMAs
    const float4* __restrict__ vt4 = (const float4*)vt;
    const int base = (ic - EE) * (DD / 4) + sub;

    unsigned long long a0 = 0ull, a1 = 0ull, a2 = 0ull, a3 = 0ull;
    #pragma unroll
    for (int k = 0; k < WW; ++k) {
        union { float4 f; unsigned long long u[2]; } V0, V1;
        V0.f = __ldg(vt4 + base + k * (DD / 4));
        V1.f = __ldg(vt4 + base + k * (DD / 4) + 8);
        const unsigned long long w2 = pack2(w[k], w[k]);
        asm("fma.rn.f32x2 %0, %1, %2, %0;" : "+l"(a0) : "l"(V0.u[0]), "l"(w2));
        asm("fma.rn.f32x2 %0, %1, %2, %0;" : "+l"(a1) : "l"(V0.u[1]), "l"(w2));
        asm("fma.rn.f32x2 %0, %1, %2, %0;" : "+l"(a2) : "l"(V1.u[0]), "l"(w2));
        asm("fma.rn.f32x2 %0, %1, %2, %0;" : "+l"(a3) : "l"(V1.u[1]), "l"(w2));
    }

    const unsigned long long inv2 = pack2(inv, inv);
    asm("mul.rn.f32x2 %0, %0, %1;" : "+l"(a0) : "l"(inv2));
    asm("mul.rn.f32x2 %0, %0, %1;" : "+l"(a1) : "l"(inv2));
    asm("mul.rn.f32x2 %0, %0, %1;" : "+l"(a2) : "l"(inv2));
    asm("mul.rn.f32x2 %0, %0, %1;" : "+l"(a3) : "l"(inv2));

    union { float4 f; unsigned long long u[2]; } O0, O1;
    O0.u[0] = a0; O0.u[1] = a1;
    O1.u[0] = a2; O1.u[1] = a3;

    float4* __restrict__ out4 = (float4*)out;
    out4[q * (DD / 4) + sub]     = O0.f;
    out4[q * (DD / 4) + sub + 8] = O1.f;
}

extern "C" void kernel_launch(void* const* d_in, const int* in_sizes, int n_in,
                              void* d_out, int out_size)
{
    const float* x  = (const float*)d_in[0];
    const float* ev = (const float*)d_in[1];
    const float* tk = (const float*)d_in[2];
    const float* vt = (const float*)d_in[3];
    float* out = (float*)d_out;

    const int B = in_sizes[0];
    const int mblocks = (B + 31) / 32;       // 8 warps * 4 queries per block

    if (B <= BMAX) {
        const int tblocks = (B + 255) / 256;
        zero_hist_kernel<<<(TT + 255) / 256, 256>>>();
        hist_kernel<<<tblocks, 256>>>(x, ev, B);
        scan_kernel<<<1, 1024>>>();
        scatter_kernel<<<tblocks, 256>>>(x, ev, B);
        hwnet_kernel<true><<<mblocks, 256>>>(x, ev, tk, vt, out, B);
    } else {
        hwnet_kernel<false><<<mblocks, 256>>>(x, ev, tk, vt, out, B);
    }
}

// round 4
// speedup vs baseline: 2.6017x; 2.6017x over previous
#include <cuda_runtime.h>
#include <cuda_bf16.h>

#define TT 2048
#define DD 64
#define EE 4
#define WW 9    // 2*EE+1

// Fused moment table: per row m (0..2047), 128 floats = 512 B:
//   [0..63]   W0[m][d] = sum_{k=-4..4} vec[m+k][d]                (f32)
//   [64..95]  W1[m][d] = sum k  * vec[m+k][d]   as bf16x2 pairs   (u32)
//   [96..127] W2[m][d] = sum k^2* vec[m+k][d]   as bf16x2 pairs   (u32)
__device__ float g_ft[TT * 128];

__device__ __forceinline__ float blo(unsigned int u) { return __uint_as_float(u << 16); }
__device__ __forceinline__ float bhi(unsigned int u) { return __uint_as_float(u & 0xFFFF0000u); }

// ---- pass 1: sliding-window moments (one thread per (row, dim-quad)) ----
__global__ void __launch_bounds__(256)
moments_kernel(const float* __restrict__ vt)
{
    const int t = blockIdx.x * blockDim.x + threadIdx.x;
    if (t >= TT * 16) return;
    const int m = t >> 4, quad = t & 15;

    float4 w0 = {0,0,0,0}, w1 = {0,0,0,0}, w2 = {0,0,0,0};
    #pragma unroll
    for (int k = -EE; k <= EE; ++k) {
        int r = min(max(m + k, 0), TT - 1);
        float4 v = __ldg((const float4*)vt + r * (DD / 4) + quad);
        const float fk = (float)k, fk2 = (float)(k * k);
        w0.x += v.x;                  w0.y += v.y;
        w0.z += v.z;                  w0.w += v.w;
        w1.x = fmaf(fk,  v.x, w1.x);  w1.y = fmaf(fk,  v.y, w1.y);
        w1.z = fmaf(fk,  v.z, w1.z);  w1.w = fmaf(fk,  v.w, w1.w);
        w2.x = fmaf(fk2, v.x, w2.x);  w2.y = fmaf(fk2, v.y, w2.y);
        w2.z = fmaf(fk2, v.z, w2.z);  w2.w = fmaf(fk2, v.w, w2.w);
    }
    float* row = g_ft + m * 128;
    ((float4*)row)[quad] = w0;

    __nv_bfloat162 p0 = __floats2bfloat162_rn(w1.x, w1.y);
    __nv_bfloat162 p1 = __floats2bfloat162_rn(w1.z, w1.w);
    uint2 u1; u1.x = *(unsigned int*)&p0; u1.y = *(unsigned int*)&p1;
    ((uint2*)(row + 64))[quad] = u1;

    __nv_bfloat162 q0 = __floats2bfloat162_rn(w2.x, w2.y);
    __nv_bfloat162 q1 = __floats2bfloat162_rn(w2.z, w2.w);
    uint2 u2; u2.x = *(unsigned int*)&q0; u2.y = *(unsigned int*)&q1;
    ((uint2*)(row + 96))[quad] = u2;
}

// ---- pass 2: main kernel. 4 queries/warp; lane sub = lane&7 owns dims [8*sub, 8*sub+8) ----
__global__ void __launch_bounds__(256)
hwnet_kernel(const float* __restrict__ x,
             const float* __restrict__ ev,
             const float* __restrict__ tk,
             const float* __restrict__ vt,
             float* __restrict__ out,
             int B)
{
    const int lane = threadIdx.x & 31;
    const int warp = threadIdx.x >> 5;
    const int g    = lane >> 3;
    const int sub  = lane & 7;

    int q = (blockIdx.x * 8 + warp) * 4 + g;
    if (q >= B) q = B - 1;                    // clamp: no lane exit, warp-sync safe

    const float xv = __ldg(x + q);
    const float e0 = __ldg(ev);
    const float eL = __ldg(ev + TT - 1);
    const float step    = (eL - e0) * (1.0f / (TT - 1));
    const float invstep = (float)(TT - 1) / (eL - e0);

    // analytic candidate verified with 3 exact-table probes (first-min tie-break)
    int cand = __float2int_rn((xv - e0) * invstep);
    cand = max(0, min(cand, TT - 1));
    const int j0 = max(cand - 1, 0);
    const int j2 = min(cand + 1, TT - 1);

    int idx = j0;
    float d  = xv - __ldg(ev + j0);
    float best = d * d;
    d = xv - __ldg(ev + cand);
    float dd = d * d;
    if (cand > j0 && dd < best) { best = dd; idx = cand; }
    d = xv - __ldg(ev + j2);
    dd = d * d;
    if (j2 > cand && dd < best) { idx = j2; }

    const float t  = __ldg(tk + idx);         // takecare at UNclipped idx (matches ref)
    const int   ic = min(max(idx, EE), TT - 1 - EE);

    float4* __restrict__ out4 = (float4*)out;
    const int obase = q * (DD / 4) + 2 * sub;

    if (__any_sync(0xFFFFFFFFu, ic != idx)) {
        // ---- exact path (clipped queries present in warp; ~1% of warps) ----
        const float d0 = (xv - e0) - (float)(ic - EE) * step;
        float w[WW], s = 0.0f;
        #pragma unroll
        for (int k = 0; k < WW; ++k) {
            float dk = d0 - (float)k * step;
            w[k] = __expf(-dk * dk * t);
            s += w[k];
        }
        const float inv = __fdividef(1.0f, s);
        const float4* __restrict__ vt4 = (const float4*)vt;
        const int base = (ic - EE) * (DD / 4) + 2 * sub;
        float4 a0 = {0,0,0,0}, a1 = {0,0,0,0};
        #pragma unroll
        for (int k = 0; k < WW; ++k) {
            float4 v0 = __ldg(vt4 + base + k * (DD / 4));
            float4 v1 = __ldg(vt4 + base + k * (DD / 4) + 1);
            const float wk = w[k];
            a0.x = fmaf(wk, v0.x, a0.x); a0.y = fmaf(wk, v0.y, a0.y);
            a0.z = fmaf(wk, v0.z, a0.z); a0.w = fmaf(wk, v0.w, a0.w);
            a1.x = fmaf(wk, v1.x, a1.x); a1.y = fmaf(wk, v1.y, a1.y);
            a1.z = fmaf(wk, v1.z, a1.z); a1.w = fmaf(wk, v1.w, a1.w);
        }
        a0.x *= inv; a0.y *= inv; a0.z *= inv; a0.w *= inv;
        a1.x *= inv; a1.y *= inv; a1.z *= inv; a1.w *= inv;
        out4[obase]     = a0;
        out4[obase + 1] = a1;
    } else {
        // ---- fast path: first-order softmax via precomputed window moments ----
        const float dc  = (xv - e0) - (float)ic * step;
        const float tdc2 = t * dc * dc;
        const float sl  = -(9.0f * tdc2 + 60.0f * t * step * step);
        const float inv = __fdividef(1.0f, 9.0f + sl);
        const float cA  = (1.0f - tdc2) * inv;
        const float cB  = (2.0f * t * dc * step) * inv;
        const float cC  = (-t * step * step) * inv;

        const float* row = g_ft + ic * 128;
        const float4 a0 = __ldg((const float4*)row + 2 * sub);
        const float4 a1 = __ldg((const float4*)row + 2 * sub + 1);
        const uint4  b1 = __ldg((const uint4*)(row + 64) + sub);
        const uint4  b2 = __ldg((const uint4*)(row + 96) + sub);

        float4 o0, o1;
        o0.x = fmaf(cA, a0.x, fmaf(cB, blo(b1.x), cC * blo(b2.x)));
        o0.y = fmaf(cA, a0.y, fmaf(cB, bhi(b1.x), cC * bhi(b2.x)));
        o0.z = fmaf(cA, a0.z, fmaf(cB, blo(b1.y), cC * blo(b2.y)));
        o0.w = fmaf(cA, a0.w, fmaf(cB, bhi(b1.y), cC * bhi(b2.y)));
        o1.x = fmaf(cA, a1.x, fmaf(cB, blo(b1.z), cC * blo(b2.z)));
        o1.y = fmaf(cA, a1.y, fmaf(cB, bhi(b1.z), cC * bhi(b2.z)));
        o1.z = fmaf(cA, a1.w == a1.w ? a1.z : a1.z, fmaf(cB, blo(b1.w), cC * blo(b2.w)));
        o1.z = fmaf(cA, a1.z, fmaf(cB, blo(b1.w), cC * blo(b2.w)));
        o1.w = fmaf(cA, a1.w, fmaf(cB, bhi(b1.w), cC * bhi(b2.w)));

        out4[obase]     = o0;
        out4[obase + 1] = o1;
    }
}

extern "C" void kernel_launch(void* const* d_in, const int* in_sizes, int n_in,
                              void* d_out, int out_size)
{
    const float* x  = (const float*)d_in[0];
    const float* ev = (const float*)d_in[1];
    const float* tk = (const float*)d_in[2];
    const float* vt = (const float*)d_in[3];
    float* out = (float*)d_out;

    const int B = in_sizes[0];
    moments_kernel<<<(TT * 16 + 255) / 256, 256>>>(vt);
    hwnet_kernel<<<(B + 31) / 32, 256>>>(x, ev, tk, vt, out, B);
}